// round 15
// baseline (speedup 1.0000x reference)
// R15: hconst atomics->warp reductions (~3us), vhull o-uniform fast-path
// output (zero layer-2 work for saturated tokens) + batched 4-token ILP,
// fused cvt. GEMM identical to R13/R14 winner. All new paths exact.
#include <cuda_runtime.h>
#include <cuda_fp16.h>
#include <cstdint>

#define BB 4
#define SS 2048
#define EE 1024
#define HH 16
#define PP 8
#define DD 64
#define NTOK (BB*SS)          // 8192
#define QSIZE (BB*HH*SS*DD)   // 8,388,608 floats per tensor
#define NQK 2048

#define C_B 2.0480546988460353f
#define C_C 0.841470984807896f
#define C_A 0.45339765151640377f
#define C_NU 0.999999327348f
#define C_EPS 1e-6f
#define SAT_T 16.0f
#define SQSP0F 0.3118852f      // sqsp(0)
#define LOG8F 2.0794415417f    // ln(8)

// ---------------------------------------------------------------------------
// Scratch
// ---------------------------------------------------------------------------
__device__ float g_Wsum1[HH*PP*DD];
__device__ float g_Wsum2[HH*PP*DD];
__device__ float g_SW2[HH*PP];     // sum_o Wsum1^2
__device__ float g_SWB[HH*PP];     // sum_o Wsum1*b1
__device__ float g_SB2m[HH*PP];    // sum_o b1^2
__device__ float g_thr1[HH];       // layer-1 saturation threshold on |s|
__device__ float g_thr2[HH];       // layer-2 saturation threshold on tp_min
__device__ int   g_b2zero[HH];     // all b2 == 0 flag
__device__ __half g_xhi[(size_t)NTOK*EE];
__device__ __half g_whi[(size_t)NQK*EE];

// ---------------------------------------------------------------------------
// helpers
// ---------------------------------------------------------------------------
__device__ __forceinline__ uint32_t smem_u32(const void* p) {
    uint32_t a;
    asm("{ .reg .u64 t; cvta.to.shared.u64 t, %1; cvt.u32.u64 %0, t; }"
        : "=r"(a) : "l"(p));
    return a;
}
__device__ __forceinline__ float warp_sum(float v) {
#pragma unroll
    for (int o = 16; o; o >>= 1) v += __shfl_xor_sync(0xffffffffu, v, o);
    return v;
}
__device__ __forceinline__ float warp_max(float v) {
#pragma unroll
    for (int o = 16; o; o >>= 1)
        v = fmaxf(v, __shfl_xor_sync(0xffffffffu, v, o));
    return v;
}
__device__ __forceinline__ float softplusf(float z) {
    float az = fabsf(z);
    float e  = __expf(-az);
    return fmaxf(z, 0.0f) + __logf(1.0f + e);
}
__device__ __forceinline__ float sqspf(float x) {
    float t1 = softplusf(C_B * x) * (1.0f / C_B);
    float t2 = softplusf(C_C * x) * (1.0f / C_C);
    float y  = (1.0f - C_A) * t1 + C_A * t2;
    return y * y;
}
__device__ __forceinline__ float sqsp_cheap(float z) {
    float p = fmaxf(z, 0.0f);
    return p * p;
}

__device__ __forceinline__ void cp16(uint32_t d, const void* s) {
    asm volatile("cp.async.cg.shared.global [%0], [%1], 16;"
                 :: "r"(d), "l"(__cvta_generic_to_global(s)) : "memory");
}
__device__ __forceinline__ void cp_commit() {
    asm volatile("cp.async.commit_group;" ::: "memory");
}
template<int N> __device__ __forceinline__ void cp_wait() {
    asm volatile("cp.async.wait_group %0;" :: "n"(N) : "memory");
}
__device__ __forceinline__ void ldsm4(uint32_t* r, uint32_t a) {
    asm volatile("ldmatrix.sync.aligned.m8n8.x4.shared.b16 {%0,%1,%2,%3}, [%4];"
                 : "=r"(r[0]), "=r"(r[1]), "=r"(r[2]), "=r"(r[3]) : "r"(a));
}
__device__ __forceinline__ void mma16816(float* d, const uint32_t* a,
                                         const uint32_t* b) {
    asm volatile(
        "mma.sync.aligned.m16n8k16.row.col.f32.f16.f16.f32 "
        "{%0,%1,%2,%3}, {%4,%5,%6,%7}, {%8,%9}, {%0,%1,%2,%3};"
        : "+f"(d[0]), "+f"(d[1]), "+f"(d[2]), "+f"(d[3])
        : "r"(a[0]), "r"(a[1]), "r"(a[2]), "r"(a[3]), "r"(b[0]), "r"(b[1]));
}

// ---------------------------------------------------------------------------
// Kernel 0: fused fp32 -> fp16 conversion for x AND qk_w
// ---------------------------------------------------------------------------
#define N4X (NTOK*EE/4)
#define N4W (NQK*EE/4)
__global__ void cvt_fused_kernel(const float4* __restrict__ x,
                                 const float4* __restrict__ w,
                                 uint2* __restrict__ xhi,
                                 uint2* __restrict__ whi) {
    int i = blockIdx.x * blockDim.x + threadIdx.x;
    float4 v;
    uint2* dst;
    if (i < N4X)            { v = x[i];        dst = xhi + i; }
    else if (i < N4X + N4W) { v = w[i - N4X];  dst = whi + (i - N4X); }
    else return;
    __half2 h01 = __float22half2_rn(make_float2(v.x, v.y));
    __half2 h23 = __float22half2_rn(make_float2(v.z, v.w));
    *dst = make_uint2(*reinterpret_cast<uint32_t*>(&h01),
                      *reinterpret_cast<uint32_t*>(&h23));
}

// ---------------------------------------------------------------------------
// Kernel 1: Wsum[h,p,o] = sum_j W[h,p,o,j]
// ---------------------------------------------------------------------------
__global__ void wsum_kernel(const float* __restrict__ W1,
                            const float* __restrict__ W2) {
    int idx  = blockIdx.x * 8 + (threadIdx.x >> 5);
    int lane = threadIdx.x & 31;
    const float* w1 = W1 + (size_t)idx * DD;
    const float* w2 = W2 + (size_t)idx * DD;
    float s1 = warp_sum(w1[lane] + w1[lane + 32]);
    float s2 = warp_sum(w2[lane] + w2[lane + 32]);
    if (lane == 0) { g_Wsum1[idx] = s1; g_Wsum2[idx] = s2; }
}

// ---------------------------------------------------------------------------
// Kernel 1b: per-head moments + thresholds (warp-per-p, no atomics)
// ---------------------------------------------------------------------------
__global__ void hconst_kernel(const float* __restrict__ b1,
                              const float* __restrict__ b2) {
    __shared__ float s_mW[PP], s_mB1[PP], s_mW2[PP], s_mB2[PP];
    int h = blockIdx.x;
    int wid = threadIdx.x >> 5;      // = p
    int lane = threadIdx.x & 31;
    int base = h * PP * DD + wid * DD;

    float w1a = g_Wsum1[base + lane],      w1b = g_Wsum1[base + lane + 32];
    float b1a = b1[base + lane],           b1b = b1[base + lane + 32];
    float w2a = g_Wsum2[base + lane],      w2b = g_Wsum2[base + lane + 32];
    float b2a = b2[base + lane],           b2b = b2[base + lane + 32];

    float sw2 = warp_sum(w1a * w1a + w1b * w1b);
    float swb = warp_sum(w1a * b1a + w1b * b1b);
    float sb2 = warp_sum(b1a * b1a + b1b * b1b);
    float mW  = warp_max(fmaxf(w1a, w1b));
    float mB1 = warp_max(fmaxf(fabsf(b1a), fabsf(b1b)));
    float mW2 = warp_max(fmaxf(w2a, w2b));
    float mB2 = warp_max(fmaxf(fabsf(b2a), fabsf(b2b)));

    if (lane == 0) {
        g_SW2[h * PP + wid]  = sw2;
        g_SWB[h * PP + wid]  = swb;
        g_SB2m[h * PP + wid] = sb2;
        s_mW[wid] = mW; s_mB1[wid] = mB1; s_mW2[wid] = mW2; s_mB2[wid] = mB2;
    }
    __syncthreads();
    if (threadIdx.x == 0) {
        float MW = s_mW[0], MB1 = s_mB1[0], MW2 = s_mW2[0], MB2 = s_mB2[0];
#pragma unroll
        for (int i = 1; i < PP; ++i) {
            MW = fmaxf(MW, s_mW[i]);   MB1 = fmaxf(MB1, s_mB1[i]);
            MW2 = fmaxf(MW2, s_mW2[i]); MB2 = fmaxf(MB2, s_mB2[i]);
        }
        g_thr1[h]   = (MW  < 0.0f) ? (SAT_T + MB1) / (-MW)  : 3.4e38f;
        g_thr2[h]   = (MW2 < 0.0f) ? (SAT_T + MB2) / (-MW2) : 3.4e38f;
        g_b2zero[h] = (MB2 == 0.0f) ? 1 : 0;
    }
}

// ---------------------------------------------------------------------------
// Kernel 2: plain fp16 GEMM (identical to R13/R14 winner)
// ---------------------------------------------------------------------------
#define BM 128
#define BN 128
#define KC 64
#define RS 144
#define SA 0
#define SB (BM*RS)
#define STAGE (2*BM*RS)
#define NSTAGE 3
#define SMEMB (NSTAGE*STAGE)
#define NCH (EE/KC)

__device__ __forceinline__ void prefetch(uint32_t sbase, int stage,
                                         int tileM, int tileN, int c, int tid) {
    uint32_t st = sbase + (uint32_t)stage * STAGE;
    int kb = c * KC;
#pragma unroll
    for (int i = 0; i < 4; ++i) {
        int idx = tid + i * 256;
        int row = idx >> 3, co = idx & 7;
        uint32_t soff = (uint32_t)(row * RS + co * 16);
        size_t ga = (size_t)(tileM * BM + row) * EE + kb + co * 8;
        size_t gb = (size_t)(tileN * BN + row) * EE + kb + co * 8;
        cp16(st + SA + soff, g_xhi + ga);
        cp16(st + SB + soff, g_whi + gb);
    }
}

__global__ __launch_bounds__(256, 2)
void qk_gemm_mma(float* __restrict__ out) {
    extern __shared__ char dsm[];
    uint32_t sbase = smem_u32(dsm);
    int tid = threadIdx.x, wid = tid >> 5, lane = tid & 31;
    int tileN = blockIdx.x, tileM = blockIdx.y;

    float acc[2][8][4];
#pragma unroll
    for (int a = 0; a < 2; ++a)
#pragma unroll
        for (int b = 0; b < 8; ++b)
#pragma unroll
            for (int cc = 0; cc < 4; ++cc) acc[a][b][cc] = 0.0f;

    prefetch(sbase, 0, tileM, tileN, 0, tid);
    cp_commit();
    prefetch(sbase, 1, tileM, tileN, 1, tid);
    cp_commit();

    int wm = (wid & 3) * 32;
    int wn = (wid >> 2) * 64;
    int r8 = lane & 7, sub = lane >> 3;

    int stage = 0;
    for (int c = 0; c < NCH; ++c) {
        cp_wait<1>();
        __syncthreads();
        if (c + 2 < NCH)
            prefetch(sbase, (stage + 2) % NSTAGE, tileM, tileN, c + 2, tid);
        cp_commit();

        uint32_t st = sbase + (uint32_t)stage * STAGE;
#pragma unroll
        for (int kk = 0; kk < 4; ++kk) {
            uint32_t ah[2][4], bh[8][2];
#pragma unroll
            for (int mt = 0; mt < 2; ++mt) {
                uint32_t ra = st + SA +
                    (uint32_t)((wm + mt * 16 + r8 + (sub & 1) * 8) * RS +
                               kk * 32 + (sub >> 1) * 16);
                ldsm4(ah[mt], ra);
            }
#pragma unroll
            for (int p = 0; p < 4; ++p) {
                uint32_t rb = st + SB +
                    (uint32_t)((wn + p * 16 + r8 + (sub >> 1) * 8) * RS +
                               kk * 32 + (sub & 1) * 16);
                uint32_t t4[4];
                ldsm4(t4, rb);
                bh[2 * p][0] = t4[0]; bh[2 * p][1] = t4[1];
                bh[2 * p + 1][0] = t4[2]; bh[2 * p + 1][1] = t4[3];
            }
#pragma unroll
            for (int mt = 0; mt < 2; ++mt)
#pragma unroll
                for (int nt = 0; nt < 8; ++nt)
                    mma16816(acc[mt][nt], ah[mt], bh[nt]);
        }
        stage = (stage + 1) % NSTAGE;
    }

    int g = lane >> 2, t2 = (lane & 3) * 2;
#pragma unroll
    for (int mt = 0; mt < 2; ++mt) {
        int mrow0 = tileM * BM + wm + mt * 16 + g;
#pragma unroll
        for (int half = 0; half < 2; ++half) {
            int m = mrow0 + half * 8;
            int b_ = m >> 11;
            int s_ = m & (SS - 1);
#pragma unroll
            for (int nt = 0; nt < 8; ++nt) {
                int j = tileN * BN + wn + nt * 8 + t2;
                size_t toff = (j >= EE) ? (size_t)QSIZE : 0;
                int jc = j & (EE - 1);
                int h  = jc >> 6;
                int d0 = jc & 63;
                float* op = out + toff +
                            (((size_t)b_ * HH + h) * SS + s_) * DD + d0;
                float2 w = make_float2(acc[mt][nt][half * 2 + 0],
                                       acc[mt][nt][half * 2 + 1]);
                *(float2*)op = w;
            }
        }
    }
}

// ---------------------------------------------------------------------------
// Kernel 3: vector-hull — batched 4-token ILP + o-uniform fast-path output
// ---------------------------------------------------------------------------
#define TOKS_PER_WARP 4

__global__ __launch_bounds__(256)
void vhull_kernel(const float* __restrict__ x,
                  const float* __restrict__ b1,
                  const float* __restrict__ b2,
                  const float* __restrict__ gate_w,
                  const float* __restrict__ gate_b,
                  float* __restrict__ vout) {
    __shared__ float sW1[PP * DD];
    __shared__ float sB1[PP * DD];
    __shared__ float sW2[PP * DD];
    __shared__ float sB2[PP * DD];
    __shared__ float sGw[DD];
    __shared__ float sSW2[PP], sSWB[PP], sSB2m[PP];

    int h = blockIdx.y;
    for (int i = threadIdx.x; i < PP * DD; i += 256) {
        sW1[i] = g_Wsum1[h * PP * DD + i];
        sB1[i] = b1[h * PP * DD + i];
        sW2[i] = g_Wsum2[h * PP * DD + i];
        sB2[i] = b2[h * PP * DD + i];
    }
    if (threadIdx.x < DD) sGw[threadIdx.x] = gate_w[h * DD + threadIdx.x];
    if (threadIdx.x < PP) {
        sSW2[threadIdx.x]  = g_SW2[h * PP + threadIdx.x];
        sSWB[threadIdx.x]  = g_SWB[h * PP + threadIdx.x];
        sSB2m[threadIdx.x] = g_SB2m[h * PP + threadIdx.x];
    }
    float gb   = gate_b[h];
    float thr1 = g_thr1[h];
    float thr2 = g_thr2[h];
    int  b2z   = g_b2zero[h];
    __syncthreads();

    int warp = threadIdx.x >> 5;
    int lane = threadIdx.x & 31;
    int tokBase = (blockIdx.x * 8 + warp) * TOKS_PER_WARP;

    float gw0 = sGw[lane], gw1 = sGw[lane + 32];

    // batched loads for all 4 tokens (independent gmem latency)
    float xa0[TOKS_PER_WARP], xa1[TOKS_PER_WARP];
#pragma unroll
    for (int t = 0; t < TOKS_PER_WARP; ++t) {
        const float* xp = x + (size_t)(tokBase + t) * EE + h * DD;
        xa0[t] = xp[lane];
        xa1[t] = xp[lane + 32];
    }

    // 3 independent reductions per token, interleaved for ILP
    float rd[TOKS_PER_WARP], rs[TOKS_PER_WARP], rq[TOKS_PER_WARP];
#pragma unroll
    for (int t = 0; t < TOKS_PER_WARP; ++t) {
        rd[t] = xa0[t] * gw0 + xa1[t] * gw1;
        rs[t] = xa0[t] + xa1[t];
        rq[t] = xa0[t] * xa0[t] + xa1[t] * xa1[t];
    }
#pragma unroll
    for (int o = 16; o; o >>= 1) {
#pragma unroll
        for (int t = 0; t < TOKS_PER_WARP; ++t) {
            rd[t] += __shfl_xor_sync(0xffffffffu, rd[t], o);
            rs[t] += __shfl_xor_sync(0xffffffffu, rs[t], o);
            rq[t] += __shfl_xor_sync(0xffffffffu, rq[t], o);
        }
    }

#pragma unroll
    for (int t = 0; t < TOKS_PER_WARP; ++t) {
        int n = tokBase + t;
        float u = sqspf(rd[t] + gb);
        float g = 1.0f - __expf(-u);
        float s  = g * rs[t];                 // sum(x*g) == g*sum(x), exact
        float q2 = g * g * rq[t];
        float tau = sqrtf(q2 * (1.0f / DD) + C_EPS + C_NU);
        float inv_tau = 1.0f / tau;

        int b_ = n >> 11;
        int s_ = n & (SS - 1);
        float* op = vout + (((size_t)b_ * HH + h) * SS + s_) * DD;

        // ---- layer 1 classification (warp-uniform branches) ----
        float tp[PP];
        bool fast = false;
        float vconst = 0.0f;
        if (s >= thr1) {                       // all z <= -16: tp = 0
#pragma unroll
            for (int p = 0; p < PP; ++p) tp[p] = 0.0f;
            if (b2z) { fast = true; vconst = SQSP0F + LOG8F * inv_tau; }
        } else if (s <= -thr1) {               // all z >= 16: moments
            float s2 = s * s, s2x = 2.0f * s;
            float tpmin = 3.4e38f;
#pragma unroll
            for (int p = 0; p < PP; ++p) {
                tp[p] = fmaf(s2, sSW2[p], fmaf(s2x, sSWB[p], sSB2m[p]));
                tpmin = fminf(tpmin, tp[p]);
            }
            if (tpmin >= thr2) { fast = true; vconst = LOG8F * inv_tau; }
        } else {                               // full layer 1
#pragma unroll
            for (int p = 0; p < PP; ++p) {
                int i0 = p * DD + lane;
                float z0 = fmaf(s, sW1[i0],      sB1[i0]);
                float z1 = fmaf(s, sW1[i0 + 32], sB1[i0 + 32]);
                bool need = (fabsf(z0) < SAT_T) || (fabsf(z1) < SAT_T);
                float y0, y1;
                if (__ballot_sync(0xffffffffu, need)) {
                    y0 = sqspf(z0);
                    y1 = sqspf(z1);
                } else {
                    y0 = sqsp_cheap(z0);
                    y1 = sqsp_cheap(z1);
                }
                tp[p] = warp_sum(y0 + y1);
            }
        }

        if (fast) {                            // o-uniform output
            op[lane]      = vconst;
            op[lane + 32] = vconst;
            continue;
        }

        // ---- layer 2 + logsumexp (fallback) ----
        float vres[2];
#pragma unroll
        for (int oo = 0; oo < 2; ++oo) {
            int o = lane + oo * 32;
            float a[PP];
            float m = -3.4e38f, mn = 3.4e38f;
#pragma unroll
            for (int p = 0; p < PP; ++p) {
                float z = fmaf(tp[p], sW2[p * DD + o], sB2[p * DD + o]);
                bool need = (fabsf(z) < SAT_T) && (z != 0.0f);
                float av;
                if (__ballot_sync(0xffffffffu, need)) av = sqspf(z);
                else av = (z == 0.0f) ? SQSP0F : sqsp_cheap(z);
                a[p] = av;
                m = fmaxf(m, av);
                mn = fminf(mn, av);
            }
            if (m == mn) {
                vres[oo] = m + LOG8F * inv_tau;
            } else {
                float sume = 0.0f;
#pragma unroll
                for (int p = 0; p < PP; ++p)
                    sume += __expf((a[p] - m) * tau);
                vres[oo] = m + __logf(sume) * inv_tau;
            }
        }
        op[lane]      = vres[0];
        op[lane + 32] = vres[1];
    }
}

// ---------------------------------------------------------------------------
// launch
// ---------------------------------------------------------------------------
extern "C" void kernel_launch(void* const* d_in, const int* in_sizes, int n_in,
                              void* d_out, int out_size) {
    const float* x      = (const float*)d_in[0];
    const float* qk_w   = (const float*)d_in[1];
    const float* W1     = (const float*)d_in[2];
    const float* b1     = (const float*)d_in[3];
    const float* W2     = (const float*)d_in[4];
    const float* b2     = (const float*)d_in[5];
    const float* gate_w = (const float*)d_in[6];
    const float* gate_b = (const float*)d_in[7];
    float* out = (float*)d_out;

    __half *xhi_p, *whi_p;
    cudaGetSymbolAddress((void**)&xhi_p, g_xhi);
    cudaGetSymbolAddress((void**)&whi_p, g_whi);

    {
        int ntot = N4X + N4W;
        cvt_fused_kernel<<<(ntot + 255) / 256, 256>>>(
            (const float4*)x, (const float4*)qk_w,
            (uint2*)xhi_p, (uint2*)whi_p);
    }

    wsum_kernel<<<1024, 256>>>(W1, W2);
    hconst_kernel<<<HH, 256>>>(b1, b2);

    cudaFuncSetAttribute(qk_gemm_mma,
                         cudaFuncAttributeMaxDynamicSharedMemorySize, SMEMB);
    dim3 ggrid(NQK / BN, NTOK / BM);   // (16, 64) = 1024 CTAs
    qk_gemm_mma<<<ggrid, 256, SMEMB>>>(out);

    dim3 vgrid(NTOK / (8 * TOKS_PER_WARP), HH);
    vhull_kernel<<<vgrid, 256>>>(x, b1, b2, gate_w, gate_b,
                                 out + 2 * (size_t)QSIZE);
}